// round 4
// baseline (speedup 1.0000x reference)
#include <cuda_runtime.h>
#include <cuda_bf16.h>

#define NG 128
#define NT 512
#define SP 28           // padded row stride (floats)
#define GSZ 320         // threads per group: 192 T + 96 H + 32 S
#define NTH 640         // 2 groups per CTA

// 24-dot, 4 independent FMA chains.
__device__ __forceinline__ float dot24(const float4* __restrict__ a, const float4* __restrict__ b) {
    float ax = 0.f, ay = 0.f, az = 0.f, aw = 0.f;
#pragma unroll
    for (int c = 0; c < 6; ++c) {
        float4 x = a[c], y = b[c];
        ax = __fmaf_rn(x.x, y.x, ax);
        ay = __fmaf_rn(x.y, y.y, ay);
        az = __fmaf_rn(x.z, y.z, az);
        aw = __fmaf_rn(x.w, y.w, aw);
    }
    return (ax + ay) + (az + aw);
}
__device__ __forceinline__ float dot24r(const float4 fr[6], const float4* __restrict__ b) {
    float ax = 0.f, ay = 0.f, az = 0.f, aw = 0.f;
#pragma unroll
    for (int c = 0; c < 6; ++c) {
        float4 y = b[c];
        ax = __fmaf_rn(fr[c].x, y.x, ax);
        ay = __fmaf_rn(fr[c].y, y.y, ay);
        az = __fmaf_rn(fr[c].z, y.z, az);
        aw = __fmaf_rn(fr[c].w, y.w, aw);
    }
    return (ax + ay) + (az + aw);
}

__device__ __forceinline__ void barx(int id, int cnt) {
    asm volatile("bar.sync %0, %1;" :: "r"(id), "r"(cnt) : "memory");
}

__global__ __launch_bounds__(NTH, 1)
void kalman_kernel(const float* __restrict__ y_in,   // (G,T,4)
                   const float* __restrict__ F_in,   // (G,T,24,24)
                   const float* __restrict__ Q_in,   // (G,T,24,24)
                   const float* __restrict__ H_in,   // (G,T,4,24)
                   const float* __restrict__ R_in,   // (G,T,4,4)
                   const float* __restrict__ m0_in,  // (G,24)
                   const float* __restrict__ P0_in,  // (G,24,24)
                   float* __restrict__ out)
{
    __shared__ __align__(16) float P  [2][24*SP];
    __shared__ __align__(16) float G1 [2][24*SP];
    __shared__ __align__(16) float Fs [2][24*SP];
    __shared__ __align__(16) float Hs [2][4*SP];
    __shared__ __align__(16) float HPs[2][4*SP];
    __shared__ __align__(16) float Bm [2][96];    // F P H^T, row i -> Bm[i*4+q]
    __shared__ __align__(16) float Sinv[2][16];
    __shared__ __align__(16) float mvec[2][24];
    __shared__ __align__(16) float Fm [2][24];
    __shared__ float Sg[2][16];
    __shared__ float Hm[2][4];
    __shared__ float resid[2][4];
    __shared__ float v4[2][4];

    const int tid = threadIdx.x;
    const int grp = (tid >= GSZ) ? 1 : 0;
    const int gt  = tid - grp * GSZ;
    const int g   = blockIdx.x * 2 + grp;
    const size_t baseT = (size_t)g * NT;
    float* outMean = out;
    float* outCov  = out + (size_t)NG * NT * 4;

    const int bT   = 1 + grp * 3;   // 192 T threads
    const int bHS  = 2 + grp * 3;   // 96 H + 32 S = 128
    const int bAll = 3 + grp * 3;   // 320

    // role-specific indices
    const int wl = gt >> 5, l = gt & 31;
    const int ti = (wl % 3) * 8 + (l & 7);          // T role (gt<192)
    const int tb = (wl / 3) * 4 + (l >> 3);         // tj in {tb, tb+8, tb+16}
    const int u  = gt - 192;                        // H role (192<=gt<288)
    const int uq = (u >= 0 && u < 96) ? u / 24 : 0;
    const int us = (u >= 0 && u < 96) ? u % 24 : 0;
    const int sl = gt - 288;                        // S role (gt>=288)

    // cofactor constants (S role lanes 0..15)
    int ca=0, cb=0, r0=0, r1=0, r2=0, c0=0, c1=0, c2=0; float csign = 1.f;
    if (sl >= 0 && sl < 16) {
        ca = sl >> 2; cb = sl & 3;
        r0 = (ca==0)?1:0; r1 = (ca<=1)?2:1; r2 = (ca<=2)?3:2;
        c0 = (cb==0)?1:0; c1 = (cb<=1)?2:1; c2 = (cb<=2)?3:2;
        csign = ((ca+cb)&1) ? -1.f : 1.f;
    }

    float qReg[3] = {0.f,0.f,0.f};
    float rCur = 0.f, yCur = 0.f;

    // ---- prologue: t = 0 ----
    if (gt < 192) {
#pragma unroll
        for (int k = 0; k < 3; ++k) {
            int idx = gt + k*192;
            P [grp][(idx/24)*SP + idx%24] = P0_in[(size_t)g*576 + idx];
            Fs[grp][(idx/24)*SP + idx%24] = F_in[baseT*576 + idx];
        }
#pragma unroll
        for (int c = 0; c < 3; ++c)
            qReg[c] = Q_in[baseT*576 + (tb + 8*c)*24 + ti];
    } else if (gt < 288) {
        Hs[grp][uq*SP + us] = H_in[baseT*96 + u];
    } else {
        if (sl < 24) mvec[grp][sl] = m0_in[g*24 + sl];
        if (sl < 16)      rCur = R_in[baseT*16 + sl];
        else if (sl < 20) yCur = y_in[baseT*4 + (sl-16)];
    }
    __syncthreads();

    float4 frow[6];
    float  fpf[3];

    for (int t = 0; t < NT; ++t) {
        // ---- prefetch t+1 ----
        float fN[3] = {0,0,0}, qN[3] = {0,0,0};
        float hN = 0.f, rN = 0.f, yN = 0.f;
        if (t + 1 < NT) {
            size_t b = baseT + t + 1;
            if (gt < 192) {
#pragma unroll
                for (int k = 0; k < 3; ++k) fN[k] = F_in[b*576 + gt + k*192];
#pragma unroll
                for (int c = 0; c < 3; ++c) qN[c] = Q_in[b*576 + (tb + 8*c)*24 + ti];
            } else if (gt < 288) {
                hN = H_in[b*96 + u];
            } else {
                if (sl < 16)      rN = R_in[b*16 + sl];
                else if (sl < 20) yN = y_in[b*4 + (sl-16)];
            }
        }

        if (gt < 192) {
            // ---- A(T): G1 rows ti: 3 dots sharing F row ti ----
            const float4* fr = (const float4*)&Fs[grp][ti*SP];
#pragma unroll
            for (int c = 0; c < 6; ++c) frow[c] = fr[c];
#pragma unroll
            for (int c = 0; c < 3; ++c)
                G1[grp][ti*SP + tb + 8*c] = dot24r(frow, (const float4*)&P[grp][(tb+8*c)*SP]);
            barx(bT, 192);
            // ---- B(T): FPF[tj][ti] = G1 row tj . F row ti + Q[tj][ti] ----
#pragma unroll
            for (int c = 0; c < 3; ++c)
                fpf[c] = qReg[c] + dot24r(frow, (const float4*)&G1[grp][(tb+8*c)*SP]);
        } else if (gt < 288) {
            // ---- A(H): HP = H @ P ----
            HPs[grp][uq*SP + us] = dot24((const float4*)&Hs[grp][uq*SP],
                                         (const float4*)&P[grp][us*SP]);
            barx(bHS, 128);
            // ---- B(H): Bm = F @ HP^T ----
            Bm[grp][us*4 + uq] = dot24((const float4*)&Fs[grp][us*SP],
                                       (const float4*)&HPs[grp][uq*SP]);
        } else {
            // ---- A(S): Hm (-> mean out), Fm ----
            if (sl < 4) {
                float hm = dot24((const float4*)&Hs[grp][sl*SP], (const float4*)mvec[grp]);
                Hm[grp][sl] = hm;
                outMean[(baseT+t)*4 + sl] = hm;
            } else if (sl < 28) {
                int i = sl - 4;
                Fm[grp][i] = dot24((const float4*)&Fs[grp][i*SP], (const float4*)mvec[grp]);
            }
            barx(bHS, 128);
            // ---- B(S): Sm -> Sig out, inverse, v4 ----
            if (sl < 16) {
                int q = sl >> 2, r = sl & 3;
                float sm = rCur + dot24((const float4*)&HPs[grp][q*SP],
                                        (const float4*)&Hs[grp][r*SP]);
                Sg[grp][sl] = sm;
                outCov[(baseT+t)*16 + sl] = sm;
            } else if (sl < 20) {
                resid[grp][sl-16] = yCur - Hm[grp][sl-16];
            }
            __syncwarp();
            if (sl < 16) {
                const float* m = Sg[grp];
                float m00=m[r0*4+c0], m01=m[r0*4+c1], m02=m[r0*4+c2];
                float m10=m[r1*4+c0], m11=m[r1*4+c1], m12=m[r1*4+c2];
                float m20=m[r2*4+c0], m21=m[r2*4+c1], m22=m[r2*4+c2];
                float d3 = m00*(m11*m22 - m12*m21)
                         - m01*(m10*m22 - m12*m20)
                         + m02*(m10*m21 - m11*m20);
                float cof = csign * d3;
                float contrib = (ca == 0) ? m[cb]*cof : 0.f;
                float det = __shfl_sync(0xffffu, contrib, 0) + __shfl_sync(0xffffu, contrib, 1)
                          + __shfl_sync(0xffffu, contrib, 2) + __shfl_sync(0xffffu, contrib, 3);
                Sinv[grp][cb*4+ca] = cof * (1.0f / det);
            }
            __syncwarp();
            if (sl < 4) {
                const float* si = Sinv[grp];
                v4[grp][sl] = si[sl*4+0]*resid[grp][0] + si[sl*4+1]*resid[grp][1]
                            + si[sl*4+2]*resid[grp][2] + si[sl*4+3]*resid[grp][3];
            }
        }
        if (t == NT-1) break;                 // uniform; last outputs already written
        barx(bAll, 320);

        // ---- D: P = FPF - B Sinv B^T ; m = Fm + B v ; stash t+1 operands ----
        if (gt < 192) {
            float4 si0 = *(const float4*)&Sinv[grp][0];
            float4 si1 = *(const float4*)&Sinv[grp][4];
            float4 si2 = *(const float4*)&Sinv[grp][8];
            float4 si3 = *(const float4*)&Sinv[grp][12];
            float4 bi  = *(const float4*)&Bm[grp][ti*4];
            float u0 = bi.x*si0.x + bi.y*si1.x + bi.z*si2.x + bi.w*si3.x;
            float u1 = bi.x*si0.y + bi.y*si1.y + bi.z*si2.y + bi.w*si3.y;
            float u2 = bi.x*si0.z + bi.y*si1.z + bi.z*si2.z + bi.w*si3.z;
            float u3 = bi.x*si0.w + bi.y*si1.w + bi.z*si2.w + bi.w*si3.w;
#pragma unroll
            for (int c = 0; c < 3; ++c) {
                float4 bj = *(const float4*)&Bm[grp][(tb+8*c)*4];
                float corr = u0*bj.x + u1*bj.y + u2*bj.z + u3*bj.w;
                P[grp][(tb+8*c)*SP + ti] = fpf[c] - corr;
            }
#pragma unroll
            for (int k = 0; k < 3; ++k) {
                int idx = gt + k*192;
                Fs[grp][(idx/24)*SP + idx%24] = fN[k];
            }
#pragma unroll
            for (int c = 0; c < 3; ++c) qReg[c] = qN[c];
        } else if (gt < 288) {
            Hs[grp][uq*SP + us] = hN;
        } else {
            if (sl < 24) {
                const float* bm = Bm[grp];
                mvec[grp][sl] = Fm[grp][sl] + bm[sl*4+0]*v4[grp][0] + bm[sl*4+1]*v4[grp][1]
                              + bm[sl*4+2]*v4[grp][2] + bm[sl*4+3]*v4[grp][3];
            }
            if (sl < 16)      rCur = rN;
            else if (sl < 20) yCur = yN;
        }
        barx(bAll, 320);
    }
}

extern "C" void kernel_launch(void* const* d_in, const int* in_sizes, int n_in,
                              void* d_out, int out_size) {
    const float* y  = (const float*)d_in[0];
    const float* F  = (const float*)d_in[1];
    const float* Q  = (const float*)d_in[2];
    const float* H  = (const float*)d_in[3];
    const float* R  = (const float*)d_in[4];
    const float* m0 = (const float*)d_in[5];
    const float* P0 = (const float*)d_in[6];
    kalman_kernel<<<NG/2, NTH>>>(y, F, Q, H, R, m0, P0, (float*)d_out);
}

// round 6
// speedup vs baseline: 1.0264x; 1.0264x over previous
#include <cuda_runtime.h>
#include <cuda_bf16.h>

#define NG 128
#define NT 512
#define SP 28            // padded row stride (floats), 16B aligned
#define NTH 416          // 288 T + 96 H + 32 S

__device__ __forceinline__ void barx(int id, int cnt) {
    asm volatile("bar.sync %0, %1;" :: "r"(id), "r"(cnt) : "memory");
}

// 24-dot, 4 independent FMA chains.
__device__ __forceinline__ float dot24(const float4* __restrict__ a, const float4* __restrict__ b) {
    float ax = 0.f, ay = 0.f, az = 0.f, aw = 0.f;
#pragma unroll
    for (int c = 0; c < 6; ++c) {
        float4 x = a[c], y = b[c];
        ax = __fmaf_rn(x.x, y.x, ax);
        ay = __fmaf_rn(x.y, y.y, ay);
        az = __fmaf_rn(x.z, y.z, az);
        aw = __fmaf_rn(x.w, y.w, aw);
    }
    return (ax + ay) + (az + aw);
}
__device__ __forceinline__ float dot24r(const float4 fr[6], const float4* __restrict__ b) {
    float ax = 0.f, ay = 0.f, az = 0.f, aw = 0.f;
#pragma unroll
    for (int c = 0; c < 6; ++c) {
        float4 y = b[c];
        ax = __fmaf_rn(fr[c].x, y.x, ax);
        ay = __fmaf_rn(fr[c].y, y.y, ay);
        az = __fmaf_rn(fr[c].z, y.z, az);
        aw = __fmaf_rn(fr[c].w, y.w, aw);
    }
    return (ax + ay) + (az + aw);
}

// 4x4 determinant, straight-line, independent chains.
__device__ __forceinline__ float det4(const float* m) {
    float s0 = m[10]*m[15] - m[11]*m[14];
    float s1 = m[9] *m[15] - m[11]*m[13];
    float s2 = m[9] *m[14] - m[10]*m[13];
    float s3 = m[8] *m[15] - m[11]*m[12];
    float s4 = m[8] *m[14] - m[10]*m[12];
    float s5 = m[8] *m[13] - m[9] *m[12];
    float c0 = m[5]*s0 - m[6]*s1 + m[7]*s2;
    float c1 = m[4]*s0 - m[6]*s3 + m[7]*s4;
    float c2 = m[4]*s1 - m[5]*s3 + m[7]*s5;
    float c3 = m[4]*s2 - m[5]*s4 + m[6]*s5;
    return m[0]*c0 - m[1]*c1 + m[2]*c2 - m[3]*c3;
}

__global__ __launch_bounds__(NTH, 1)
void kalman_kernel(const float* __restrict__ y_in,   // (G,T,4)
                   const float* __restrict__ F_in,   // (G,T,24,24)
                   const float* __restrict__ Q_in,   // (G,T,24,24)
                   const float* __restrict__ H_in,   // (G,T,4,24)
                   const float* __restrict__ R_in,   // (G,T,4,4)
                   const float* __restrict__ m0_in,  // (G,24)
                   const float* __restrict__ P0_in,  // (G,24,24)
                   float* __restrict__ out)
{
    __shared__ __align__(16) float P  [24*SP];
    __shared__ __align__(16) float G1 [24*SP];
    __shared__ __align__(16) float Fs [24*SP];
    __shared__ __align__(16) float Hs [4*SP];
    __shared__ __align__(16) float HPs[4*SP];
    __shared__ __align__(16) float Bm [96];      // (F P H^T), row i -> Bm[i*4+q]
    __shared__ __align__(16) float Sinv[16];
    __shared__ __align__(16) float mvec[24];
    __shared__ __align__(16) float Fm [24];
    __shared__ float Sg[16];
    __shared__ float Hm[4];
    __shared__ float ys[2][4];
    __shared__ float v4[4];

    const int tid = threadIdx.x;
    const int g   = blockIdx.x;
    const size_t baseT = (size_t)g * NT;
    float* outMean = out;
    float* outCov  = out + (size_t)NG * NT * 4;

    // role indices
    const int w  = tid >> 5, l = tid & 31;
    const int ti  = (w % 3) * 8 + (l & 7);           // T role (tid<288): row
    const int tjp = (w / 3) * 4 + (l >> 3);          // col base; cols {tjp, tjp+12}
    const int u  = tid - 288;                        // H role (288<=tid<384)
    const int uq = (u >= 0 && u < 96) ? (u / 24) : 0;
    const int us = (u >= 0 && u < 96) ? (u % 24) : 0;
    const int sl = tid - 384;                        // S role (tid>=384), lanes 0..31

    // cofactor constants (S lanes 0..15): element (ca,cb) of Sinv^T handling
    int ca=0, cb=0, r0=0, r1=0, r2=0, c0=0, c1=0, c2=0; float csign = 1.f;
    if (sl >= 0 && sl < 16) {
        ca = sl >> 2; cb = sl & 3;
        r0 = (ca==0)?1:0; r1 = (ca<=1)?2:1; r2 = (ca<=2)?3:2;
        c0 = (cb==0)?1:0; c1 = (cb<=1)?2:1; c2 = (cb<=2)?3:2;
        csign = ((ca+cb)&1) ? -1.f : 1.f;
    }

    float qReg[2] = {0.f, 0.f};
    float rCur = 0.f;

    // ---- prologue: t = 0 ----
    if (tid < 288) {
#pragma unroll
        for (int k = 0; k < 2; ++k) {
            int idx = tid + k*288;
            P [(idx/24)*SP + idx%24] = P0_in[(size_t)g*576 + idx];
            Fs[(idx/24)*SP + idx%24] = F_in[baseT*576 + idx];
        }
#pragma unroll
        for (int c = 0; c < 2; ++c)
            qReg[c] = Q_in[baseT*576 + (tjp + 12*c)*24 + ti];
    } else if (tid < 384) {
        Hs[uq*SP + us] = H_in[baseT*96 + u];
    } else {
        if (sl < 24) mvec[sl] = m0_in[g*24 + sl];
        if (sl < 16)      rCur = R_in[baseT*16 + sl];
        else if (sl < 20) ys[0][sl-16] = y_in[baseT*4 + (sl-16)];
    }
    __syncthreads();

    float4 frow[6];
    float  fpf[2];

    for (int t = 0; t < NT; ++t) {
        // ---- prefetch t+1 ----
        float fN[2] = {0,0}, qN[2] = {0,0};
        float hN = 0.f, rN = 0.f, yN = 0.f;
        if (t + 1 < NT) {
            size_t b = baseT + t + 1;
            if (tid < 288) {
#pragma unroll
                for (int k = 0; k < 2; ++k) fN[k] = F_in[b*576 + tid + k*288];
#pragma unroll
                for (int c = 0; c < 2; ++c) qN[c] = Q_in[b*576 + (tjp + 12*c)*24 + ti];
            } else if (tid < 384) {
                hN = H_in[b*96 + u];
            } else {
                if (sl < 16)      rN = R_in[b*16 + sl];
                else if (sl < 20) yN = y_in[b*4 + (sl-16)];
            }
        }

        if (tid < 288) {
            // ---- A(T): G1[ti][tj] = F row ti . P row tj (P symmetric) ----
            const float4* fr = (const float4*)&Fs[ti*SP];
#pragma unroll
            for (int c = 0; c < 6; ++c) frow[c] = fr[c];
#pragma unroll
            for (int c = 0; c < 2; ++c)
                G1[ti*SP + tjp + 12*c] = dot24r(frow, (const float4*)&P[(tjp+12*c)*SP]);
            barx(1, 288);
            // ---- B(T): FPF[tj][ti] = G1 row tj . F row ti + Q[tj][ti] ----
#pragma unroll
            for (int c = 0; c < 2; ++c)
                fpf[c] = qReg[c] + dot24r(frow, (const float4*)&G1[(tjp+12*c)*SP]);
        } else if (tid < 384) {
            // ---- A(H): HP = H @ P ----
            HPs[uq*SP + us] = dot24((const float4*)&Hs[uq*SP], (const float4*)&P[us*SP]);
            barx(2, 128);
            // ---- B(H): Bm = F @ HP^T ----
            Bm[us*4 + uq] = dot24((const float4*)&Fs[us*SP], (const float4*)&HPs[uq*SP]);
        } else {
            // ---- A(S): Hm (-> mean out), Fm ----
            if (sl < 4) {
                float hm = dot24((const float4*)&Hs[sl*SP], (const float4*)mvec);
                Hm[sl] = hm;
                outMean[(baseT+t)*4 + sl] = hm;
            } else if (sl < 28) {
                int i = sl - 4;
                Fm[i] = dot24((const float4*)&Fs[i*SP], (const float4*)mvec);
            }
            barx(2, 128);
            // ---- B(S): Sm -> Sig out; Sinv (no shuffles) ----
            if (sl < 16) {
                int q = sl >> 2, r = sl & 3;
                float sm = rCur + dot24((const float4*)&HPs[q*SP], (const float4*)&Hs[r*SP]);
                Sg[sl] = sm;
                outCov[(baseT+t)*16 + sl] = sm;
            }
            __syncwarp();
            if (sl < 16) {
                // cofactor for (ca,cb) + redundant det from Sg; independent chains
                const float* m = Sg;
                float m00=m[r0*4+c0], m01=m[r0*4+c1], m02=m[r0*4+c2];
                float m10=m[r1*4+c0], m11=m[r1*4+c1], m12=m[r1*4+c2];
                float m20=m[r2*4+c0], m21=m[r2*4+c1], m22=m[r2*4+c2];
                float d3 = m00*(m11*m22 - m12*m21)
                         - m01*(m10*m22 - m12*m20)
                         + m02*(m10*m21 - m11*m20);
                float det = det4(m);
                Sinv[cb*4+ca] = csign * d3 * (1.0f / det);
            }
        }
        if (t == NT-1) break;    // last step's outputs already written in A/B
        __syncthreads();

        // ---- D: P = FPF - B Sinv B^T ; S-warp tail overlaps; stash t+1 ----
        if (tid < 288) {
            float4 si0 = *(const float4*)&Sinv[0];
            float4 si1 = *(const float4*)&Sinv[4];
            float4 si2 = *(const float4*)&Sinv[8];
            float4 si3 = *(const float4*)&Sinv[12];
            float4 bi  = *(const float4*)&Bm[ti*4];
            float u0 = bi.x*si0.x + bi.y*si1.x + bi.z*si2.x + bi.w*si3.x;
            float u1 = bi.x*si0.y + bi.y*si1.y + bi.z*si2.y + bi.w*si3.y;
            float u2 = bi.x*si0.z + bi.y*si1.z + bi.z*si2.z + bi.w*si3.z;
            float u3 = bi.x*si0.w + bi.y*si1.w + bi.z*si2.w + bi.w*si3.w;
#pragma unroll
            for (int c = 0; c < 2; ++c) {
                float4 bj = *(const float4*)&Bm[(tjp+12*c)*4];
                float corr = u0*bj.x + u1*bj.y + u2*bj.z + u3*bj.w;
                P[(tjp+12*c)*SP + ti] = fpf[c] - corr;
            }
#pragma unroll
            for (int k = 0; k < 2; ++k) {
                int idx = tid + k*288;
                Fs[(idx/24)*SP + idx%24] = fN[k];
            }
            qReg[0] = qN[0]; qReg[1] = qN[1];
        } else if (tid < 384) {
            Hs[uq*SP + us] = hN;
        } else {
            // S-warp tail: v4 = Sinv (y - Hm); then m' = Fm + B v4
            if (sl < 4) {
                const float* si = &Sinv[sl*4];
                const float* yb = ys[t & 1];
                v4[sl] = si[0]*(yb[0]-Hm[0]) + si[1]*(yb[1]-Hm[1])
                       + si[2]*(yb[2]-Hm[2]) + si[3]*(yb[3]-Hm[3]);
            }
            __syncwarp();
            if (sl < 24) {
                mvec[sl] = Fm[sl] + Bm[sl*4+0]*v4[0] + Bm[sl*4+1]*v4[1]
                         + Bm[sl*4+2]*v4[2] + Bm[sl*4+3]*v4[3];
            }
            if (sl < 16)      rCur = rN;
            else if (sl < 20) ys[(t+1) & 1][sl-16] = yN;
        }
        __syncthreads();
    }
}

extern "C" void kernel_launch(void* const* d_in, const int* in_sizes, int n_in,
                              void* d_out, int out_size) {
    const float* y  = (const float*)d_in[0];
    const float* F  = (const float*)d_in[1];
    const float* Q  = (const float*)d_in[2];
    const float* H  = (const float*)d_in[3];
    const float* R  = (const float*)d_in[4];
    const float* m0 = (const float*)d_in[5];
    const float* P0 = (const float*)d_in[6];
    kalman_kernel<<<NG, NTH>>>(y, F, Q, H, R, m0, P0, (float*)d_out);
}

// round 7
// speedup vs baseline: 1.0522x; 1.0252x over previous
#include <cuda_runtime.h>
#include <cuda_bf16.h>

#define NG 128
#define NT 512
#define SP 28          // padded row stride (floats) = 112B, 16B-aligned
#define NTH 704        // 576 T + 96 H + 32 S

#define BAR_T()  asm volatile("bar.sync 1, 576;" ::: "memory")
#define BAR_HS() asm volatile("bar.sync 2, 128;" ::: "memory")

typedef unsigned long long u64t;

// packed f32x2 FMA: d = a*b + d (per 32-bit lane), sm_100+ PTX
__device__ __forceinline__ void fma2(u64t& d, u64t a, u64t b) {
    asm("fma.rn.f32x2 %0, %1, %2, %3;" : "=l"(d) : "l"(a), "l"(b), "l"(d));
}

// 24-dot via 12 FFMA2 in 2 independent chains. Pointers must be 16B-aligned smem.
__device__ __forceinline__ float dot24p(const ulonglong2* __restrict__ a,
                                        const ulonglong2* __restrict__ b) {
    u64t a0 = 0ull, a1 = 0ull;
#pragma unroll
    for (int c = 0; c < 6; ++c) {
        ulonglong2 x = a[c], y = b[c];
        fma2(a0, x.x, y.x);
        fma2(a1, x.y, y.y);
    }
    float2 f0 = *reinterpret_cast<float2*>(&a0);
    float2 f1 = *reinterpret_cast<float2*>(&a1);
    return (f0.x + f0.y) + (f1.x + f1.y);
}
// same, first operand register-cached
__device__ __forceinline__ float dot24pr(const ulonglong2 fr[6],
                                         const ulonglong2* __restrict__ b) {
    u64t a0 = 0ull, a1 = 0ull;
#pragma unroll
    for (int c = 0; c < 6; ++c) {
        ulonglong2 y = b[c];
        fma2(a0, fr[c].x, y.x);
        fma2(a1, fr[c].y, y.y);
    }
    float2 f0 = *reinterpret_cast<float2*>(&a0);
    float2 f1 = *reinterpret_cast<float2*>(&a1);
    return (f0.x + f0.y) + (f1.x + f1.y);
}

// 4x4 determinant, straight-line independent chains (no shuffles).
__device__ __forceinline__ float det4(const float* m) {
    float s0 = m[10]*m[15] - m[11]*m[14];
    float s1 = m[9] *m[15] - m[11]*m[13];
    float s2 = m[9] *m[14] - m[10]*m[13];
    float s3 = m[8] *m[15] - m[11]*m[12];
    float s4 = m[8] *m[14] - m[10]*m[12];
    float s5 = m[8] *m[13] - m[9] *m[12];
    float c0 = m[5]*s0 - m[6]*s1 + m[7]*s2;
    float c1 = m[4]*s0 - m[6]*s3 + m[7]*s4;
    float c2 = m[4]*s1 - m[5]*s3 + m[7]*s5;
    float c3 = m[4]*s2 - m[5]*s4 + m[6]*s5;
    return m[0]*c0 - m[1]*c1 + m[2]*c2 - m[3]*c3;
}

__global__ __launch_bounds__(NTH, 1)
void kalman_kernel(const float* __restrict__ y_in,   // (G,T,4)
                   const float* __restrict__ F_in,   // (G,T,24,24)
                   const float* __restrict__ Q_in,   // (G,T,24,24)
                   const float* __restrict__ H_in,   // (G,T,4,24)
                   const float* __restrict__ R_in,   // (G,T,4,4)
                   const float* __restrict__ m0_in,  // (G,24)
                   const float* __restrict__ P0_in,  // (G,24,24)
                   float* __restrict__ out)
{
    __shared__ __align__(16) float P  [24*SP];
    __shared__ __align__(16) float G1 [24*SP];
    __shared__ __align__(16) float Fs [24*SP];
    __shared__ __align__(16) float Hs [4*SP];
    __shared__ __align__(16) float HPs[4*SP];
    __shared__ __align__(16) float Bm [96];      // (F P H^T), row i -> Bm[i*4+q]
    __shared__ __align__(16) float Sinv[16];
    __shared__ __align__(16) float mvec[24];
    __shared__ __align__(16) float Fm [24];
    __shared__ __align__(16) float Sg[16];
    __shared__ float Hm[4];
    __shared__ float ys[2][4];
    __shared__ float v4[4];

    const int tid = threadIdx.x;
    const int g   = blockIdx.x;
    const size_t baseT = (size_t)g * NT;
    float* outMean = out;
    float* outCov  = out + (size_t)NG * NT * 4;

    // role indices
    const int w = tid >> 5, l = tid & 31;
    const int ti = (w % 3) * 8 + (l & 7);    // T role (tid<576)
    const int tj = (w / 3) * 4 + (l >> 3);
    const int li = tid / 24, lj = tid % 24;  // coalesced load map
    const int u  = tid - 576;                // H role
    const int uq = (u >= 0 && u < 96) ? u / 24 : 0;
    const int us = (u >= 0 && u < 96) ? u % 24 : 0;
    const int sl = tid - 672;                // S role

    // cofactor constants (S lanes 0..15)
    int ca=0, cb=0, r0=0, r1=0, r2=0, c0=0, c1=0, c2=0; float csign = 1.f;
    if (sl >= 0 && sl < 16) {
        ca = sl >> 2; cb = sl & 3;
        r0 = (ca==0)?1:0; r1 = (ca<=1)?2:1; r2 = (ca<=2)?3:2;
        c0 = (cb==0)?1:0; c1 = (cb<=1)?2:1; c2 = (cb<=2)?3:2;
        csign = ((ca+cb)&1) ? -1.f : 1.f;
    }

    float qCur = 0.f, rCur = 0.f;

    // ---- prologue: t = 0 ----
    if (tid < 576) {
        P [li*SP+lj] = P0_in[(size_t)g*576 + tid];
        Fs[li*SP+lj] = F_in[baseT*576 + tid];
        qCur = Q_in[baseT*576 + tj*24 + ti];     // Q[tj][ti]
        if (tid < 24) mvec[tid] = m0_in[g*24 + tid];
    } else if (tid < 672) {
        Hs[uq*SP + us] = H_in[baseT*96 + u];
    } else {
        if (sl < 16)      rCur = R_in[baseT*16 + sl];
        else if (sl < 20) ys[0][sl-16] = y_in[baseT*4 + (sl-16)];
    }
    __syncthreads();

    ulonglong2 frow[6];     // packed F row ti, cached A -> B
    float fpfReg = 0.f;     // FPF[tj][ti] carried B -> D

    for (int t = 0; t < NT; ++t) {
        // ---- prefetch t+1 (consumed in stage D) ----
        float fN = 0.f, qN = 0.f, hN = 0.f, rN = 0.f, yN = 0.f;
        if (t + 1 < NT) {
            size_t b = baseT + t + 1;
            if (tid < 576)      { fN = F_in[b*576 + tid]; qN = Q_in[b*576 + tj*24 + ti]; }
            else if (tid < 672)   hN = H_in[b*96 + u];
            else {
                if (sl < 16)      rN = R_in[b*16 + sl];
                else if (sl < 20) yN = y_in[b*4 + (sl-16)];
            }
        }

        if (tid < 576) {
            // ---- A(T): G1[ti][tj] = F row ti . P row tj  (P symmetric) ----
            const ulonglong2* fr = (const ulonglong2*)&Fs[ti*SP];
#pragma unroll
            for (int c = 0; c < 6; ++c) frow[c] = fr[c];
            G1[ti*SP+tj] = dot24pr(frow, (const ulonglong2*)&P[tj*SP]);
            BAR_T();
            // ---- B(T): FPF[tj][ti] = G1 row tj . F row ti + Q[tj][ti] ----
            fpfReg = qCur + dot24pr(frow, (const ulonglong2*)&G1[tj*SP]);
        } else if (tid < 672) {
            // ---- A(H): HP = H @ P ----
            HPs[uq*SP+us] = dot24p((const ulonglong2*)&Hs[uq*SP],
                                   (const ulonglong2*)&P[us*SP]);
            BAR_HS();
            // ---- B(H): Bm = F @ HP^T ----
            Bm[us*4 + uq] = dot24p((const ulonglong2*)&Fs[us*SP],
                                   (const ulonglong2*)&HPs[uq*SP]);
        } else {
            // ---- A(S): Hm (-> mean out), Fm ----
            if (sl < 4) {
                float hm = dot24p((const ulonglong2*)&Hs[sl*SP], (const ulonglong2*)mvec);
                Hm[sl] = hm;
                outMean[(baseT+t)*4 + sl] = hm;
            } else if (sl < 28) {
                int i = sl - 4;
                Fm[i] = dot24p((const ulonglong2*)&Fs[i*SP], (const ulonglong2*)mvec);
            }
            BAR_HS();
            // ---- B(S): Sm -> Sig out; Sinv (redundant det, no shuffles) ----
            if (sl < 16) {
                int q = sl >> 2, r = sl & 3;
                float sm = rCur + dot24p((const ulonglong2*)&HPs[q*SP],
                                         (const ulonglong2*)&Hs[r*SP]);
                Sg[sl] = sm;
                outCov[(baseT+t)*16 + sl] = sm;
            }
            __syncwarp();
            if (sl < 16) {
                const float* m = Sg;
                float m00=m[r0*4+c0], m01=m[r0*4+c1], m02=m[r0*4+c2];
                float m10=m[r1*4+c0], m11=m[r1*4+c1], m12=m[r1*4+c2];
                float m20=m[r2*4+c0], m21=m[r2*4+c1], m22=m[r2*4+c2];
                float d3 = m00*(m11*m22 - m12*m21)
                         - m01*(m10*m22 - m12*m20)
                         + m02*(m10*m21 - m11*m20);
                float det = det4(m);
                Sinv[cb*4+ca] = csign * d3 * (1.0f / det);
            }
        }
        if (t == NT-1) break;   // last step's outputs already written
        __syncthreads();

        // ---- D: P = FPF - B Sinv B^T ; S tail (v4, m') overlaps; stash t+1 ----
        if (tid < 576) {
            float4 si0 = *(const float4*)&Sinv[0];
            float4 si1 = *(const float4*)&Sinv[4];
            float4 si2 = *(const float4*)&Sinv[8];
            float4 si3 = *(const float4*)&Sinv[12];
            float4 bi  = *(const float4*)&Bm[ti*4];
            float u0 = bi.x*si0.x + bi.y*si1.x + bi.z*si2.x + bi.w*si3.x;
            float u1 = bi.x*si0.y + bi.y*si1.y + bi.z*si2.y + bi.w*si3.y;
            float u2 = bi.x*si0.z + bi.y*si1.z + bi.z*si2.z + bi.w*si3.z;
            float u3 = bi.x*si0.w + bi.y*si1.w + bi.z*si2.w + bi.w*si3.w;
            float4 bj = *(const float4*)&Bm[tj*4];
            float corr = u0*bj.x + u1*bj.y + u2*bj.z + u3*bj.w;
            P[tj*SP+ti] = fpfReg - corr;     // symmetric: transposed slot
            Fs[li*SP+lj] = fN;
            qCur = qN;
        } else if (tid < 672) {
            Hs[uq*SP + us] = hN;
        } else {
            if (sl < 4) {
                const float* si = &Sinv[sl*4];
                const float* yb = ys[t & 1];
                v4[sl] = si[0]*(yb[0]-Hm[0]) + si[1]*(yb[1]-Hm[1])
                       + si[2]*(yb[2]-Hm[2]) + si[3]*(yb[3]-Hm[3]);
            }
            __syncwarp();
            if (sl < 24) {
                mvec[sl] = Fm[sl] + Bm[sl*4+0]*v4[0] + Bm[sl*4+1]*v4[1]
                         + Bm[sl*4+2]*v4[2] + Bm[sl*4+3]*v4[3];
            }
            if (sl < 16)      rCur = rN;
            else if (sl < 20) ys[(t+1) & 1][sl-16] = yN;
        }
        __syncthreads();
    }
}

extern "C" void kernel_launch(void* const* d_in, const int* in_sizes, int n_in,
                              void* d_out, int out_size) {
    const float* y  = (const float*)d_in[0];
    const float* F  = (const float*)d_in[1];
    const float* Q  = (const float*)d_in[2];
    const float* H  = (const float*)d_in[3];
    const float* R  = (const float*)d_in[4];
    const float* m0 = (const float*)d_in[5];
    const float* P0 = (const float*)d_in[6];
    kalman_kernel<<<NG, NTH>>>(y, F, Q, H, R, m0, P0, (float*)d_out);
}

// round 9
// speedup vs baseline: 1.0754x; 1.0221x over previous
#include <cuda_runtime.h>
#include <cuda_bf16.h>

#define NG 128
#define NT 512
#define SP 28          // padded row stride (floats) = 112B, 16B-aligned
#define NTH 704        // 576 T + 96 H + 32 S

#define BAR_SYNC(id,n)   asm volatile("bar.sync %0, %1;"   :: "r"(id), "r"(n) : "memory")
#define BAR_ARRIVE(id,n) asm volatile("bar.arrive %0, %1;" :: "r"(id), "r"(n) : "memory")

// 24-dot with 4 independent FMA chains + tree reduce.
__device__ __forceinline__ float dot24(const float4* __restrict__ a, const float4* __restrict__ b) {
    float ax = 0.f, ay = 0.f, az = 0.f, aw = 0.f;
#pragma unroll
    for (int c = 0; c < 6; ++c) {
        float4 x = a[c], y = b[c];
        ax = __fmaf_rn(x.x, y.x, ax);
        ay = __fmaf_rn(x.y, y.y, ay);
        az = __fmaf_rn(x.z, y.z, az);
        aw = __fmaf_rn(x.w, y.w, aw);
    }
    return (ax + ay) + (az + aw);
}
__device__ __forceinline__ float dot24r(const float4 fr[6], const float4* __restrict__ b) {
    float ax = 0.f, ay = 0.f, az = 0.f, aw = 0.f;
#pragma unroll
    for (int c = 0; c < 6; ++c) {
        float4 y = b[c];
        ax = __fmaf_rn(fr[c].x, y.x, ax);
        ay = __fmaf_rn(fr[c].y, y.y, ay);
        az = __fmaf_rn(fr[c].z, y.z, az);
        aw = __fmaf_rn(fr[c].w, y.w, aw);
    }
    return (ax + ay) + (az + aw);
}

// 4x4 determinant, straight-line, independent chains (no shuffles).
__device__ __forceinline__ float det4(const float* m) {
    float s0 = m[10]*m[15] - m[11]*m[14];
    float s1 = m[9] *m[15] - m[11]*m[13];
    float s2 = m[9] *m[14] - m[10]*m[13];
    float s3 = m[8] *m[15] - m[11]*m[12];
    float s4 = m[8] *m[14] - m[10]*m[12];
    float s5 = m[8] *m[13] - m[9] *m[12];
    float c0 = m[5]*s0 - m[6]*s1 + m[7]*s2;
    float c1 = m[4]*s0 - m[6]*s3 + m[7]*s4;
    float c2 = m[4]*s1 - m[5]*s3 + m[7]*s5;
    float c3 = m[4]*s2 - m[5]*s4 + m[6]*s5;
    return m[0]*c0 - m[1]*c1 + m[2]*c2 - m[3]*c3;
}

__global__ __launch_bounds__(NTH, 1)
void kalman_kernel(const float* __restrict__ y_in,   // (G,T,4)
                   const float* __restrict__ F_in,   // (G,T,24,24)
                   const float* __restrict__ Q_in,   // (G,T,24,24)
                   const float* __restrict__ H_in,   // (G,T,4,24)
                   const float* __restrict__ R_in,   // (G,T,4,4)
                   const float* __restrict__ m0_in,  // (G,24)
                   const float* __restrict__ P0_in,  // (G,24,24)
                   float* __restrict__ out)
{
    __shared__ __align__(16) float P  [24*SP];
    __shared__ __align__(16) float G1 [24*SP];
    __shared__ __align__(16) float Fs [24*SP];
    __shared__ __align__(16) float Hs [2][4*SP];   // double-buffered
    __shared__ __align__(16) float HPs[4*SP];
    __shared__ __align__(16) float Bm [96];        // (F P H^T), row i -> Bm[i*4+q]
    __shared__ __align__(16) float Sinv[16];
    __shared__ __align__(16) float mvec[24];
    __shared__ __align__(16) float Fm [24];
    __shared__ __align__(16) float Sg[16];
    __shared__ float Hm[4];
    __shared__ float ys[2][4];
    __shared__ float v4[4];

    const int tid = threadIdx.x;
    const int g   = blockIdx.x;
    const size_t baseT = (size_t)g * NT;
    float* outMean = out;
    float* outCov  = out + (size_t)NG * NT * 4;

    // role indices
    const int w = tid >> 5, l = tid & 31;
    const int ti = (w % 3) * 8 + (l & 7);    // T role (tid<576)
    const int tj = (w / 3) * 4 + (l >> 3);
    const int li = tid / 24, lj = tid % 24;  // coalesced load map
    const int u  = tid - 576;                // H role
    const int uq = (u >= 0 && u < 96) ? u / 24 : 0;
    const int us = (u >= 0 && u < 96) ? u % 24 : 0;
    const int sl = tid - 672;                // S role

    // cofactor constants (S lanes 0..15)
    int ca=0, cb=0, r0=0, r1=0, r2=0, c0=0, c1=0, c2=0; float csign = 1.f;
    if (sl >= 0 && sl < 16) {
        ca = sl >> 2; cb = sl & 3;
        r0 = (ca==0)?1:0; r1 = (ca<=1)?2:1; r2 = (ca<=2)?3:2;
        c0 = (cb==0)?1:0; c1 = (cb<=1)?2:1; c2 = (cb<=2)?3:2;
        csign = ((ca+cb)&1) ? -1.f : 1.f;
    }

    float qCur = 0.f, rCur = 0.f;

    // ---- prologue: t = 0 ----
    if (tid < 576) {
        P [li*SP+lj] = P0_in[(size_t)g*576 + tid];
        Fs[li*SP+lj] = F_in[baseT*576 + tid];
        qCur = Q_in[baseT*576 + tj*24 + ti];     // Q[tj][ti]
        if (tid < 24) mvec[tid] = m0_in[g*24 + tid];
    } else if (tid < 672) {
        Hs[0][uq*SP + us] = H_in[baseT*96 + u];
    } else {
        if (sl < 16)      rCur = R_in[baseT*16 + sl];
        else if (sl < 20) ys[0][sl-16] = y_in[baseT*4 + (sl-16)];
    }
    __syncthreads();

    float4 frow[6];       // F row ti, cached A -> B
    float  fpfReg = 0.f;  // FPF[tj][ti] carried B -> D

    for (int t = 0; t < NT; ++t) {
        const int cur = t & 1, nxt = cur ^ 1;

        // ---- prefetch t+1 (consumed in stage D) ----
        float fN = 0.f, qN = 0.f, hN = 0.f, rN = 0.f, yN = 0.f;
        if (t + 1 < NT) {
            size_t b = baseT + t + 1;
            if (tid < 576)      { fN = F_in[b*576 + tid]; qN = Q_in[b*576 + tj*24 + ti]; }
            else if (tid < 672)   hN = H_in[b*96 + u];
            else {
                if (sl < 16)      rN = R_in[b*16 + sl];
                else if (sl < 20) yN = y_in[b*4 + (sl-16)];
            }
        }

        // ================= stages A + B (role-parallel) =================
        if (tid < 576) {
            // A(T): G1[ti][tj] = F row ti . P row tj  (P symmetric)
            const float4* fr = (const float4*)&Fs[ti*SP];
#pragma unroll
            for (int c = 0; c < 6; ++c) frow[c] = fr[c];
            G1[ti*SP+tj] = dot24r(frow, (const float4*)&P[tj*SP]);
            BAR_SYNC(1, 576);
            // B(T): FPF[tj][ti] = G1 row tj . F row ti + Q[tj][ti]
            fpfReg = qCur + dot24r(frow, (const float4*)&G1[tj*SP]);
        } else if (tid < 672) {
            // A(H): HP = H @ P
            HPs[uq*SP+us] = dot24((const float4*)&Hs[cur][uq*SP],
                                  (const float4*)&P[us*SP]);
            BAR_SYNC(2, 128);
            // B(H): Bm = F @ HP^T
            Bm[us*4 + uq] = dot24((const float4*)&Fs[us*SP],
                                  (const float4*)&HPs[uq*SP]);
        } else {
            // A(S): Hm (-> mean out), Fm
            if (sl < 4) {
                float hm = dot24((const float4*)&Hs[cur][sl*SP], (const float4*)mvec);
                Hm[sl] = hm;
                outMean[(baseT+t)*4 + sl] = hm;
            } else if (sl < 28) {
                int i = sl - 4;
                Fm[i] = dot24((const float4*)&Fs[i*SP], (const float4*)mvec);
            }
            BAR_SYNC(2, 128);
            // B(S): Sm -> Sig out; Sinv via redundant det (no shuffles)
            if (sl < 16) {
                int q = sl >> 2, r = sl & 3;
                float sm = rCur + dot24((const float4*)&HPs[q*SP],
                                        (const float4*)&Hs[cur][r*SP]);
                Sg[sl] = sm;
                outCov[(baseT+t)*16 + sl] = sm;
            }
            __syncwarp();
            if (sl < 16) {
                const float* m = Sg;
                float m00=m[r0*4+c0], m01=m[r0*4+c1], m02=m[r0*4+c2];
                float m10=m[r1*4+c0], m11=m[r1*4+c1], m12=m[r1*4+c2];
                float m20=m[r2*4+c0], m21=m[r2*4+c1], m22=m[r2*4+c2];
                float d3 = m00*(m11*m22 - m12*m21)
                         - m01*(m10*m22 - m12*m20)
                         + m02*(m10*m21 - m11*m20);
                float det = det4(m);
                Sinv[cb*4+ca] = csign * d3 * (1.0f / det);
            }
        }
        if (t == NT-1) break;   // uniform; last step's outputs already written

        // ================= stage D (producer/consumer barriers) =================
        if (tid < 576) {
            BAR_SYNC(3, 704);                  // wait for Bm (H) + Sinv (S)
            float4 si0 = *(const float4*)&Sinv[0];
            float4 si1 = *(const float4*)&Sinv[4];
            float4 si2 = *(const float4*)&Sinv[8];
            float4 si3 = *(const float4*)&Sinv[12];
            float4 bi  = *(const float4*)&Bm[ti*4];
            float u0 = bi.x*si0.x + bi.y*si1.x + bi.z*si2.x + bi.w*si3.x;
            float u1 = bi.x*si0.y + bi.y*si1.y + bi.z*si2.y + bi.w*si3.y;
            float u2 = bi.x*si0.z + bi.y*si1.z + bi.z*si2.z + bi.w*si3.z;
            float u3 = bi.x*si0.w + bi.y*si1.w + bi.z*si2.w + bi.w*si3.w;
            float4 bj = *(const float4*)&Bm[tj*4];
            float corr = u0*bj.x + u1*bj.y + u2*bj.z + u3*bj.w;
            P[tj*SP+ti] = fpfReg - corr;      // symmetric: transposed slot
            Fs[li*SP+lj] = fN;                // safe: H/S arrived bar3 after reads
            qCur = qN;
        } else if (tid < 672) {
            BAR_ARRIVE(4, 128);                // let S read Bm
            BAR_ARRIVE(3, 704);                // let T proceed; H doesn't block
            Hs[nxt][uq*SP + us] = hN;          // double buffer: no race with S reads
        } else {
            BAR_ARRIVE(3, 704);                // Sinv published; don't wait for T
            BAR_SYNC(4, 128);                  // wait for Bm only
            if (sl < 4) {
                const float* si = &Sinv[sl*4];
                const float* yb = ys[cur];
                v4[sl] = si[0]*(yb[0]-Hm[0]) + si[1]*(yb[1]-Hm[1])
                       + si[2]*(yb[2]-Hm[2]) + si[3]*(yb[3]-Hm[3]);
            }
            __syncwarp();
            if (sl < 24) {
                mvec[sl] = Fm[sl] + Bm[sl*4+0]*v4[0] + Bm[sl*4+1]*v4[1]
                         + Bm[sl*4+2]*v4[2] + Bm[sl*4+3]*v4[3];
            }
            if (sl < 16)      rCur = rN;
            else if (sl < 20) ys[nxt][sl-16] = yN;
        }
        __syncthreads();
    }
}

extern "C" void kernel_launch(void* const* d_in, const int* in_sizes, int n_in,
                              void* d_out, int out_size) {
    const float* y  = (const float*)d_in[0];
    const float* F  = (const float*)d_in[1];
    const float* Q  = (const float*)d_in[2];
    const float* H  = (const float*)d_in[3];
    const float* R  = (const float*)d_in[4];
    const float* m0 = (const float*)d_in[5];
    const float* P0 = (const float*)d_in[6];
    kalman_kernel<<<NG, NTH>>>(y, F, Q, H, R, m0, P0, (float*)d_out);
}

// round 10
// speedup vs baseline: 1.2573x; 1.1691x over previous
#include <cuda_runtime.h>
#include <cuda_bf16.h>

#define NG 128
#define NT 512
#define SP 28          // padded row stride (floats) = 112B, 16B-aligned
#define NTH 704        // 576 T + 96 H + 32 S

#define BSYNC(id,n)  asm volatile("bar.sync %0, %1;"   :: "n"(id), "r"(n) : "memory")
#define BARRV(id,n)  asm volatile("bar.arrive %0, %1;" :: "n"(id), "r"(n) : "memory")
#define BSYNCR(id,n) asm volatile("bar.sync %0, %1;"   :: "r"(id), "r"(n) : "memory")

// 24-dot with 4 independent FMA chains + tree reduce.
__device__ __forceinline__ float dot24(const float4* __restrict__ a, const float4* __restrict__ b) {
    float ax = 0.f, ay = 0.f, az = 0.f, aw = 0.f;
#pragma unroll
    for (int c = 0; c < 6; ++c) {
        float4 x = a[c], y = b[c];
        ax = __fmaf_rn(x.x, y.x, ax);
        ay = __fmaf_rn(x.y, y.y, ay);
        az = __fmaf_rn(x.z, y.z, az);
        aw = __fmaf_rn(x.w, y.w, aw);
    }
    return (ax + ay) + (az + aw);
}
__device__ __forceinline__ float dot24r(const float4 fr[6], const float4* __restrict__ b) {
    float ax = 0.f, ay = 0.f, az = 0.f, aw = 0.f;
#pragma unroll
    for (int c = 0; c < 6; ++c) {
        float4 y = b[c];
        ax = __fmaf_rn(fr[c].x, y.x, ax);
        ay = __fmaf_rn(fr[c].y, y.y, ay);
        az = __fmaf_rn(fr[c].z, y.z, az);
        aw = __fmaf_rn(fr[c].w, y.w, aw);
    }
    return (ax + ay) + (az + aw);
}

// 4x4 determinant, straight-line, independent chains (no shuffles).
__device__ __forceinline__ float det4(const float* m) {
    float s0 = m[10]*m[15] - m[11]*m[14];
    float s1 = m[9] *m[15] - m[11]*m[13];
    float s2 = m[9] *m[14] - m[10]*m[13];
    float s3 = m[8] *m[15] - m[11]*m[12];
    float s4 = m[8] *m[14] - m[10]*m[12];
    float s5 = m[8] *m[13] - m[9] *m[12];
    float c0 = m[5]*s0 - m[6]*s1 + m[7]*s2;
    float c1 = m[4]*s0 - m[6]*s3 + m[7]*s4;
    float c2 = m[4]*s1 - m[5]*s3 + m[7]*s5;
    float c3 = m[4]*s2 - m[5]*s4 + m[6]*s5;
    return m[0]*c0 - m[1]*c1 + m[2]*c2 - m[3]*c3;
}

__global__ __launch_bounds__(NTH, 1)
void kalman_kernel(const float* __restrict__ y_in,   // (G,T,4)
                   const float* __restrict__ F_in,   // (G,T,24,24)
                   const float* __restrict__ Q_in,   // (G,T,24,24)
                   const float* __restrict__ H_in,   // (G,T,4,24)
                   const float* __restrict__ R_in,   // (G,T,4,4)
                   const float* __restrict__ m0_in,  // (G,24)
                   const float* __restrict__ P0_in,  // (G,24,24)
                   float* __restrict__ out)
{
    __shared__ __align__(16) float P  [24*SP];
    __shared__ __align__(16) float G1 [2][24*SP];  // double-buffered
    __shared__ __align__(16) float Fs [2][24*SP];  // double-buffered
    __shared__ __align__(16) float Hs [2][4*SP];   // double-buffered
    __shared__ __align__(16) float HPs[4*SP];
    __shared__ __align__(16) float Bm [96];        // (F P H^T), row i -> Bm[i*4+q]
    __shared__ __align__(16) float Sinv[16];
    __shared__ __align__(16) float mvec[24];
    __shared__ __align__(16) float Fm [24];
    __shared__ __align__(16) float Sg[16];
    __shared__ float Hm[4];
    __shared__ float ys[2][4];
    __shared__ float v4[4];

    const int tid = threadIdx.x;
    const int g   = blockIdx.x;
    const size_t baseT = (size_t)g * NT;
    float* outMean = out;
    float* outCov  = out + (size_t)NG * NT * 4;

    const int w = tid >> 5, l = tid & 31;

    if (tid < 576) {
        // =================== T role: covariance propagation ===================
        const int ti  = (w % 3) * 8 + (l & 7);
        const int tj  = (w / 3) * 4 + (l >> 3);
        const int blk = w / 3;                     // 6 blocks x 3 warps; block owns P rows [4blk,4blk+4)
        const int li  = tid / 24, lj = tid % 24;   // flat coalesced map
        const int bid = 8 + blk;

        P [li*SP+lj]     = P0_in[(size_t)g*576 + tid];
        Fs[0][li*SP+lj]  = F_in[baseT*576 + tid];
        float qCur       = Q_in[baseT*576 + tj*24 + ti];
        if (tid < 24) mvec[tid] = m0_in[g*24 + tid];
        BSYNC(0, 704);

        const float* pF = F_in + baseT*576 + 576 + tid;
        const float* pQ = Q_in + baseT*576 + 576 + tj*24 + ti;
        float4 frow[6];

        for (int t = 0; t < NT-1; ++t) {
            const int cur = t & 1, nxt = cur ^ 1;
            float fN = *pF; pF += 576;
            float qN = *pQ; pQ += 576;

            // ---- A: G1[ti][tj] = F row ti . P row tj  (P symmetric) ----
            const float4* fr = (const float4*)&Fs[cur][ti*SP];
#pragma unroll
            for (int c = 0; c < 6; ++c) frow[c] = fr[c];
            G1[cur][ti*SP+tj] = dot24r(frow, (const float4*)&P[tj*SP]);
            BSYNC(1, 576);

            // ---- B: FPF[tj][ti] = G1 row tj . F row ti + Q[tj][ti]; stash F ----
            float fpf = qCur + dot24r(frow, (const float4*)&G1[cur][tj*SP]);
            Fs[nxt][li*SP+lj] = fN;
            qCur = qN;
            BSYNC(3, 704);                 // wait Bm (H arrive) + Sinv (S sync)

            // ---- D: P[tj][ti] = fpf - b_i Sinv b_j^T ----
            float4 si0 = *(const float4*)&Sinv[0];
            float4 si1 = *(const float4*)&Sinv[4];
            float4 si2 = *(const float4*)&Sinv[8];
            float4 si3 = *(const float4*)&Sinv[12];
            float4 bi  = *(const float4*)&Bm[ti*4];
            float u0 = bi.x*si0.x + bi.y*si1.x + bi.z*si2.x + bi.w*si3.x;
            float u1 = bi.x*si0.y + bi.y*si1.y + bi.z*si2.y + bi.w*si3.y;
            float u2 = bi.x*si0.z + bi.y*si1.z + bi.z*si2.z + bi.w*si3.z;
            float u3 = bi.x*si0.w + bi.y*si1.w + bi.z*si2.w + bi.w*si3.w;
            float4 bj = *(const float4*)&Bm[tj*4];
            float corr = u0*bj.x + u1*bj.y + u2*bj.z + u3*bj.w;
            P[tj*SP+ti] = fpf - corr;

            BARRV(7, 672);                 // let H see completed P
            BSYNCR(bid, 96);               // only our tj-block must converge
        }
        // T not needed for the final step's outputs.
    } else if (tid < 672) {
        // =================== H role: HP = H P,  Bm = F (HP)^T ===================
        const int u = tid - 576, uq = u / 24, us = u % 24;

        Hs[0][uq*SP + us] = H_in[baseT*96 + u];
        BSYNC(0, 704);

        const float* pH = H_in + baseT*96 + 96 + u;

        for (int t = 0; t < NT-1; ++t) {
            const int cur = t & 1, nxt = cur ^ 1;
            float hN = *pH; pH += 96;

            HPs[uq*SP+us] = dot24((const float4*)&Hs[cur][uq*SP],
                                  (const float4*)&P[us*SP]);
            BSYNC(2, 128);

            Bm[us*4 + uq] = dot24((const float4*)&Fs[cur][us*SP],
                                  (const float4*)&HPs[uq*SP]);
            Hs[nxt][uq*SP + us] = hN;
            BARRV(4, 128);                 // S may read Bm
            BARRV(3, 704);                 // T may read Bm
            BSYNC(7, 672);                 // wait for new P before next HP
        }
        // epilogue t = NT-1: HP for the final Sigma
        {
            const int cur = (NT-1) & 1;
            HPs[uq*SP+us] = dot24((const float4*)&Hs[cur][uq*SP],
                                  (const float4*)&P[us*SP]);
            BSYNC(2, 128);
        }
    } else {
        // =================== S role: measurement, inverse, mean ===================
        const int sl = tid - 672;

        int ca=0, cb=0, r0=0, r1=0, r2=0, c0=0, c1=0, c2=0; float csign = 1.f;
        if (sl < 16) {
            ca = sl >> 2; cb = sl & 3;
            r0 = (ca==0)?1:0; r1 = (ca<=1)?2:1; r2 = (ca<=2)?3:2;
            c0 = (cb==0)?1:0; c1 = (cb<=1)?2:1; c2 = (cb<=2)?3:2;
            csign = ((ca+cb)&1) ? -1.f : 1.f;
        }

        float rCur = 0.f;
        if (sl < 16)              rCur = R_in[baseT*16 + sl];
        else if (sl < 20)         ys[0][sl-16] = y_in[baseT*4 + (sl-16)];
        BSYNC(0, 704);

        const float* pR = R_in + baseT*16 + 16 + sl;
        const float* pY = y_in + baseT*4  + 4  + (sl - 16);

        for (int t = 0; t < NT-1; ++t) {
            const int cur = t & 1, nxt = cur ^ 1;
            float rN = 0.f, yN = 0.f;
            if (sl < 16)      rN = *pR;
            else if (sl < 20) yN = *pY;
            pR += 16; pY += 4;

            // ---- A: Hm (-> mean out), Fm ----
            if (sl < 4) {
                float hm = dot24((const float4*)&Hs[cur][sl*SP], (const float4*)mvec);
                Hm[sl] = hm;
                outMean[(baseT+t)*4 + sl] = hm;
            } else if (sl < 28) {
                int i = sl - 4;
                Fm[i] = dot24((const float4*)&Fs[cur][i*SP], (const float4*)mvec);
            }
            BSYNC(2, 128);

            // ---- B: Sm -> Sig out; Sinv (redundant det, no shuffles) ----
            if (sl < 16) {
                int q = sl >> 2, r = sl & 3;
                float sm = rCur + dot24((const float4*)&HPs[q*SP],
                                        (const float4*)&Hs[cur][r*SP]);
                Sg[sl] = sm;
                outCov[(baseT+t)*16 + sl] = sm;
            }
            __syncwarp();
            if (sl < 16) {
                const float* m = Sg;
                float m00=m[r0*4+c0], m01=m[r0*4+c1], m02=m[r0*4+c2];
                float m10=m[r1*4+c0], m11=m[r1*4+c1], m12=m[r1*4+c2];
                float m20=m[r2*4+c0], m21=m[r2*4+c1], m22=m[r2*4+c2];
                float d3 = m00*(m11*m22 - m12*m21)
                         - m01*(m10*m22 - m12*m20)
                         + m02*(m10*m21 - m11*m20);
                float det = det4(m);
                Sinv[cb*4+ca] = csign * d3 * (1.0f / det);
            }
            BSYNC(3, 704);                 // publish Sinv; also orders T's Fs stash
            BSYNC(4, 128);                 // wait Bm from H

            // ---- D (off critical path): v4, m' ----
            if (sl < 4) {
                const float* si = &Sinv[sl*4];
                const float* yb = ys[cur];
                v4[sl] = si[0]*(yb[0]-Hm[0]) + si[1]*(yb[1]-Hm[1])
                       + si[2]*(yb[2]-Hm[2]) + si[3]*(yb[3]-Hm[3]);
            }
            __syncwarp();
            if (sl < 24) {
                mvec[sl] = Fm[sl] + Bm[sl*4+0]*v4[0] + Bm[sl*4+1]*v4[1]
                         + Bm[sl*4+2]*v4[2] + Bm[sl*4+3]*v4[3];
            }
            rCur = rN;
            if (sl >= 16 && sl < 20) ys[nxt][sl-16] = yN;
            __syncwarp();                  // mvec visible to next A
        }
        // epilogue t = NT-1: final mean + Sigma
        {
            const int cur = (NT-1) & 1;
            if (sl < 4) {
                float hm = dot24((const float4*)&Hs[cur][sl*SP], (const float4*)mvec);
                outMean[(baseT+NT-1)*4 + sl] = hm;
            }
            BSYNC(2, 128);
            if (sl < 16) {
                int q = sl >> 2, r = sl & 3;
                float sm = rCur + dot24((const float4*)&HPs[q*SP],
                                        (const float4*)&Hs[cur][r*SP]);
                outCov[(baseT+NT-1)*16 + sl] = sm;
            }
        }
    }
}

extern "C" void kernel_launch(void* const* d_in, const int* in_sizes, int n_in,
                              void* d_out, int out_size) {
    const float* y  = (const float*)d_in[0];
    const float* F  = (const float*)d_in[1];
    const float* Q  = (const float*)d_in[2];
    const float* H  = (const float*)d_in[3];
    const float* R  = (const float*)d_in[4];
    const float* m0 = (const float*)d_in[5];
    const float* P0 = (const float*)d_in[6];
    kalman_kernel<<<NG, NTH>>>(y, F, Q, H, R, m0, P0, (float*)d_out);
}